// round 1
// baseline (speedup 1.0000x reference)
#include <cuda_runtime.h>
#include <cfloat>
#include <cstdint>

// ResidualCodebook: z -> (z@Wq+bq) -> 4x residual VQ over K=4096 codebook -> (@Wp+bp)
// Shapes: z [32768,512] f32, Wq [512,64], bq [64], codebooks [4,4096,64], Wp [64,512], bp [512]
// out [32768,512] f32.
//
// Numeric fidelity notes (argmin stability vs the fp32 jax reference):
//   d = (sum(r^2) + e_sq[k]) - 2*(r . e_k), computed with exactly that fp32 op order,
//   dots accumulated sequentially over d=0..63 with fmaf, residual/z_q updates in fp32,
//   argmin tie-break = lowest index.

#define N_TOK  32768
#define IN_D   512
#define D_LAT  64
#define K_CB   4096
#define H_CB   4

__device__ float g_residual[N_TOK * D_LAT];   // 8 MB scratch
__device__ float g_esq[H_CB * K_CB];

// ---------------- kernel A: e_sq[h][k] = sum_d cb[h][k][d]^2 ----------------
__global__ void esq_kernel(const float* __restrict__ cb) {
    int warp = (blockIdx.x * blockDim.x + threadIdx.x) >> 5;
    int lane = threadIdx.x & 31;
    if (warp >= H_CB * K_CB) return;
    const float* row = cb + (size_t)warp * D_LAT;
    float x0 = row[lane], x1 = row[lane + 32];
    float a = x0 * x0 + x1 * x1;
    #pragma unroll
    for (int off = 16; off; off >>= 1) a += __shfl_down_sync(0xffffffffu, a, off);
    if (lane == 0) g_esq[warp] = a;
}

// ---------------- kernel B: residual = z @ Wq + bq ----------------
// block: 128 tokens x 64 latent, 128 threads, 8x8 thread tiles, K-chunks of 32.
__global__ void __launch_bounds__(128) proj_in_kernel(const float* __restrict__ z,
                                                      const float* __restrict__ Wq,
                                                      const float* __restrict__ bq) {
    __shared__ float zs[128 * 36];   // [t][i] padded row stride 36 floats
    __shared__ float wst[64 * 36];   // [l][i] transposed Wq chunk

    int tid = threadIdx.x;
    int tt = tid & 15;        // 16 token-threads (tokens tt+16j)
    int lt = tid >> 4;        // 8 lat-threads  (lats lt*8+i, consecutive)
    int tok0 = blockIdx.x * 128;

    float acc[8][8];
    #pragma unroll
    for (int j = 0; j < 8; ++j)
        #pragma unroll
        for (int i = 0; i < 8; ++i) acc[j][i] = 0.f;

    for (int ch = 0; ch < 16; ++ch) {
        __syncthreads();
        // load z chunk [128 tok][32 in] (float4, coalesced)
        #pragma unroll
        for (int s = 0; s < 8; ++s) {
            int id = tid + 128 * s;          // 0..1023
            int t = id >> 3, q = id & 7;
            float4 v = *(const float4*)(z + (size_t)(tok0 + t) * IN_D + ch * 32 + q * 4);
            *(float4*)(zs + t * 36 + q * 4) = v;
        }
        // load Wq chunk transposed: wst[l][i] = Wq[ch*32+i][l]
        #pragma unroll
        for (int s = 0; s < 16; ++s) {
            int id = tid + 128 * s;          // 0..2047
            int l = id & 63, i = id >> 6;
            wst[l * 36 + i] = Wq[(size_t)(ch * 32 + i) * D_LAT + l];
        }
        __syncthreads();

        #pragma unroll
        for (int iq = 0; iq < 8; ++iq) {
            float4 zv[8];
            #pragma unroll
            for (int j = 0; j < 8; ++j)
                zv[j] = *(const float4*)(zs + (tt + 16 * j) * 36 + iq * 4);
            #pragma unroll
            for (int i = 0; i < 8; ++i) {
                float4 wv = *(const float4*)(wst + (lt * 8 + i) * 36 + iq * 4);
                #pragma unroll
                for (int j = 0; j < 8; ++j) {
                    float a = acc[j][i];
                    a = fmaf(zv[j].x, wv.x, a);
                    a = fmaf(zv[j].y, wv.y, a);
                    a = fmaf(zv[j].z, wv.z, a);
                    a = fmaf(zv[j].w, wv.w, a);
                    acc[j][i] = a;
                }
            }
        }
    }

    // write residual rows (+bq), two float4 per token
    #pragma unroll
    for (int j = 0; j < 8; ++j) {
        int t = tok0 + tt + 16 * j;
        int l0 = lt * 8;
        float4 o0 = make_float4(acc[j][0] + bq[l0 + 0], acc[j][1] + bq[l0 + 1],
                                acc[j][2] + bq[l0 + 2], acc[j][3] + bq[l0 + 3]);
        float4 o1 = make_float4(acc[j][4] + bq[l0 + 4], acc[j][5] + bq[l0 + 5],
                                acc[j][6] + bq[l0 + 6], acc[j][7] + bq[l0 + 7]);
        *(float4*)(g_residual + (size_t)t * D_LAT + l0)     = o0;
        *(float4*)(g_residual + (size_t)t * D_LAT + l0 + 4) = o1;
    }
}

// ---------------- kernel C: residual VQ (4 steps) + final projection ----------------
// block: 64 tokens, 256 threads = 8 token-threads x 32 k-threads, 8x8 tiles, K-chunks of 256.
#define SMEM_FLOATS (64*68 /*rs*/ + 64*68 /*zqs*/ + 256*68 /*es*/ + 256 /*esq*/ + 64 /*rsq*/ \
                     + 64*32 /*bestv*/ + 64*32 /*besti*/ + 64 /*idx*/)
#define SMEM_BYTES  (SMEM_FLOATS * 4)

__global__ void __launch_bounds__(256, 1) rcq_kernel(const float* __restrict__ cb,
                                                     const float* __restrict__ Wp,
                                                     const float* __restrict__ bp,
                                                     float* __restrict__ out) {
    extern __shared__ float sm[];
    float* rs    = sm;                      // [64][68]
    float* zqs   = rs + 64 * 68;            // [64][68]
    float* es    = zqs + 64 * 68;           // [256][68]  (reused as wps in phase 3)
    float* esqS  = es + 256 * 68;           // [256]
    float* rsqS  = esqS + 256;              // [64]
    float* bestv = rsqS + 64;               // [64][32]
    int*   besti = (int*)(bestv + 64 * 32); // [64][32]
    int*   idxS  = besti + 64 * 32;         // [64]

    int tid = threadIdx.x;
    int tt = tid & 7;       // token-thread: tokens tt+8j
    int kg = tid >> 3;      // k-thread (32): ks kg+32i within chunk
    int tok0 = blockIdx.x * 64;

    // init rs from global residual, zqs = 0
    #pragma unroll
    for (int s = 0; s < 4; ++s) {
        int id = tid + 256 * s;        // 0..1023
        int t = id >> 4, q = id & 15;
        float4 v = *(const float4*)(g_residual + (size_t)(tok0 + t) * D_LAT + q * 4);
        *(float4*)(rs + t * 68 + q * 4)  = v;
        *(float4*)(zqs + t * 68 + q * 4) = make_float4(0.f, 0.f, 0.f, 0.f);
    }
    __syncthreads();

    for (int h = 0; h < H_CB; ++h) {
        // rsq[t] = sum_d r[t][d]^2, sequential d
        if (tid < 64) {
            const float* r = rs + tid * 68;
            float a = 0.f;
            #pragma unroll
            for (int d = 0; d < 64; ++d) a = fmaf(r[d], r[d], a);
            rsqS[tid] = a;
        }
        float bv[8]; int bi[8];
        #pragma unroll
        for (int j = 0; j < 8; ++j) { bv[j] = FLT_MAX; bi[j] = 0x7fffffff; }

        for (int ch = 0; ch < 16; ++ch) {
            __syncthreads();
            int kbase = ch * 256;
            const float* cbh = cb + ((size_t)h * K_CB + kbase) * D_LAT;
            // load E chunk [256][64] -> es[r][d], padded stride 68
            #pragma unroll
            for (int s = 0; s < 16; ++s) {
                int id = tid + 256 * s;     // 0..4095
                int r = id >> 4, q = id & 15;
                float4 v = *(const float4*)(cbh + (size_t)r * D_LAT + q * 4);
                *(float4*)(es + r * 68 + q * 4) = v;
            }
            esqS[tid] = g_esq[h * K_CB + kbase + tid];
            __syncthreads();

            float acc[8][8];
            #pragma unroll
            for (int j = 0; j < 8; ++j)
                #pragma unroll
                for (int i = 0; i < 8; ++i) acc[j][i] = 0.f;

            #pragma unroll 4
            for (int dq = 0; dq < 16; ++dq) {
                float4 rv[8];
                #pragma unroll
                for (int j = 0; j < 8; ++j)
                    rv[j] = *(const float4*)(rs + (tt + 8 * j) * 68 + dq * 4);
                #pragma unroll
                for (int i = 0; i < 8; ++i) {
                    float4 ev = *(const float4*)(es + (kg + 32 * i) * 68 + dq * 4);
                    #pragma unroll
                    for (int j = 0; j < 8; ++j) {
                        float a = acc[j][i];
                        a = fmaf(rv[j].x, ev.x, a);
                        a = fmaf(rv[j].y, ev.y, a);
                        a = fmaf(rv[j].z, ev.z, a);
                        a = fmaf(rv[j].w, ev.w, a);
                        acc[j][i] = a;
                    }
                }
            }
            // argmin update with reference-exact rounding:
            // d = fl(fl(rsq + e_sq) - fl(2*dot)), tie -> lowest index
            #pragma unroll
            for (int j = 0; j < 8; ++j) {
                float rq = rsqS[tt + 8 * j];
                #pragma unroll
                for (int i = 0; i < 8; ++i) {
                    int kk = kbase + kg + 32 * i;
                    float dv = (rq + esqS[kg + 32 * i]) - 2.0f * acc[j][i];
                    if (dv < bv[j] || (dv == bv[j] && kk < bi[j])) { bv[j] = dv; bi[j] = kk; }
                }
            }
        }
        #pragma unroll
        for (int j = 0; j < 8; ++j) {
            bestv[(tt + 8 * j) * 32 + kg] = bv[j];
            besti[(tt + 8 * j) * 32 + kg] = bi[j];
        }
        __syncthreads();
        if (tid < 64) {
            float v = bestv[tid * 32]; int bidx = besti[tid * 32];
            for (int g = 1; g < 32; ++g) {
                float vv = bestv[tid * 32 + g]; int ii = besti[tid * 32 + g];
                if (vv < v || (vv == v && ii < bidx)) { v = vv; bidx = ii; }
            }
            idxS[tid] = bidx;
        }
        __syncthreads();
        // gather + update: zq += e, r -= e (4 threads per token, 16 d each)
        {
            int t = tid >> 2, q0 = (tid & 3) * 4;
            const float* e = cb + ((size_t)h * K_CB + idxS[t]) * D_LAT;
            #pragma unroll
            for (int q = 0; q < 4; ++q) {
                float4 ev = *(const float4*)(e + (q0 + q) * 4);
                float* zp = zqs + t * 68 + (q0 + q) * 4;
                float* rp = rs + t * 68 + (q0 + q) * 4;
                float4 zv = *(float4*)zp;
                float4 rw = *(float4*)rp;
                zv.x += ev.x; zv.y += ev.y; zv.z += ev.z; zv.w += ev.w;
                rw.x -= ev.x; rw.y -= ev.y; rw.z -= ev.z; rw.w -= ev.w;
                *(float4*)zp = zv;
                *(float4*)rp = rw;
            }
        }
        __syncthreads();
    }

    // ---------------- phase 3: out = zqs @ Wp + bp ----------------
    float* wps = es;   // reuse as [c][d] padded stride 68
    for (int co = 0; co < IN_D; co += 256) {
        __syncthreads();
        #pragma unroll 8
        for (int s = 0; s < 64; ++s) {
            int id = tid + 256 * s;      // 0..16383: d = id>>8, c = id&255
            int d = id >> 8, c = id & 255;
            wps[c * 68 + d] = Wp[(size_t)d * IN_D + co + c];
        }
        __syncthreads();

        float acc[8][8];
        #pragma unroll
        for (int j = 0; j < 8; ++j)
            #pragma unroll
            for (int i = 0; i < 8; ++i) acc[j][i] = 0.f;

        #pragma unroll 4
        for (int dq = 0; dq < 16; ++dq) {
            float4 zv[8];
            #pragma unroll
            for (int j = 0; j < 8; ++j)
                zv[j] = *(const float4*)(zqs + (tt + 8 * j) * 68 + dq * 4);
            #pragma unroll
            for (int i = 0; i < 8; ++i) {
                float4 wv = *(const float4*)(wps + (kg * 8 + i) * 68 + dq * 4);
                #pragma unroll
                for (int j = 0; j < 8; ++j) {
                    float a = acc[j][i];
                    a = fmaf(zv[j].x, wv.x, a);
                    a = fmaf(zv[j].y, wv.y, a);
                    a = fmaf(zv[j].z, wv.z, a);
                    a = fmaf(zv[j].w, wv.w, a);
                    acc[j][i] = a;
                }
            }
        }
        #pragma unroll
        for (int j = 0; j < 8; ++j) {
            int t = tok0 + tt + 8 * j;
            int c0 = co + kg * 8;
            float4 o0 = make_float4(acc[j][0] + bp[c0 + 0], acc[j][1] + bp[c0 + 1],
                                    acc[j][2] + bp[c0 + 2], acc[j][3] + bp[c0 + 3]);
            float4 o1 = make_float4(acc[j][4] + bp[c0 + 4], acc[j][5] + bp[c0 + 5],
                                    acc[j][6] + bp[c0 + 6], acc[j][7] + bp[c0 + 7]);
            *(float4*)(out + (size_t)t * IN_D + c0)     = o0;
            *(float4*)(out + (size_t)t * IN_D + c0 + 4) = o1;
        }
        __syncthreads();
    }
}

// ---------------- launcher ----------------
extern "C" void kernel_launch(void* const* d_in, const int* in_sizes, int n_in,
                              void* d_out, int out_size) {
    const float* z  = (const float*)d_in[0];
    const float* Wq = (const float*)d_in[1];
    const float* bq = (const float*)d_in[2];
    const float* cb = (const float*)d_in[3];
    const float* Wp = (const float*)d_in[4];
    const float* bp = (const float*)d_in[5];
    float* out = (float*)d_out;

    cudaFuncSetAttribute(rcq_kernel, cudaFuncAttributeMaxDynamicSharedMemorySize, SMEM_BYTES);

    esq_kernel<<<(H_CB * K_CB * 32 + 255) / 256, 256>>>(cb);
    proj_in_kernel<<<N_TOK / 128, 128>>>(z, Wq, bq);
    rcq_kernel<<<N_TOK / 64, 256, SMEM_BYTES>>>(cb, Wp, bp, out);
}

// round 3
// speedup vs baseline: 1.0817x; 1.0817x over previous
#include <cuda_runtime.h>
#include <cfloat>
#include <cstdint>

// ResidualCodebook: z -> (z@Wq+bq) -> 4x residual VQ over K=4096 -> (@Wp+bp)
// z [32768,512] f32, Wq [512,64], bq[64], codebooks [4,4096,64], Wp [64,512], bp[512]
//
// Exactness: all FMA chains keep the reference's sequential-d fp32 order.
// fma.rn.f32x2 packs two INDEPENDENT tokens (or output lanes) per instruction;
// each lane is a bit-exact fp32 FMA, so results are bit-identical to round-1.

#define N_TOK  32768
#define IN_D   512
#define D_LAT  64
#define K_CB   4096
#define H_CB   4

#define ES_STR 68     // padded row stride (floats) for [k][d] tiles
#define RP_STR 132    // padded row stride (floats) for token-pair rows (64 float2 + pad)

__device__ float g_residual[N_TOK * D_LAT];
__device__ float g_esq[H_CB * K_CB];

// ---- packed fp32x2 FMA (Blackwell; each lane exact IEEE fp32 fma) ----
__device__ __forceinline__ float2 ffma2(float2 a, float2 b, float2 c) {
    unsigned long long ua = *(unsigned long long*)&a;
    unsigned long long ub = *(unsigned long long*)&b;
    unsigned long long uc = *(unsigned long long*)&c;
    unsigned long long ud;
    asm("fma.rn.f32x2 %0, %1, %2, %3;" : "=l"(ud) : "l"(ua), "l"(ub), "l"(uc));
    return *(float2*)&ud;
}

// ---- cp.async helpers ----
__device__ __forceinline__ void cpa16(void* dst, const void* src) {
    unsigned d = (unsigned)__cvta_generic_to_shared(dst);
    asm volatile("cp.async.cg.shared.global [%0], [%1], 16;\n" :: "r"(d), "l"(src));
}
__device__ __forceinline__ void cp_commit() { asm volatile("cp.async.commit_group;\n"); }
template<int N> __device__ __forceinline__ void cp_wait() {
    asm volatile("cp.async.wait_group %0;\n" :: "n"(N));
}

// ---------------- kernel A: e_sq ----------------
__global__ void esq_kernel(const float* __restrict__ cb) {
    int warp = (blockIdx.x * blockDim.x + threadIdx.x) >> 5;
    int lane = threadIdx.x & 31;
    if (warp >= H_CB * K_CB) return;
    const float* row = cb + (size_t)warp * D_LAT;
    float x0 = row[lane], x1 = row[lane + 32];
    float a = x0 * x0 + x1 * x1;
    #pragma unroll
    for (int off = 16; off; off >>= 1) a += __shfl_down_sync(0xffffffffu, a, off);
    if (lane == 0) g_esq[warp] = a;
}

// ---------------- kernel B: residual = z @ Wq + bq (f32x2, paired over latent) ----------------
__global__ void __launch_bounds__(128) proj_in_kernel(const float* __restrict__ z,
                                                      const float* __restrict__ Wq,
                                                      const float* __restrict__ bq) {
    __shared__ float zs[128 * 36];   // [t][i]
    __shared__ float ws[32 * ES_STR];// [i][l], l contiguous (natural Wq layout)

    int tid = threadIdx.x;
    int tt = tid & 15;
    int lt = tid >> 4;
    int tok0 = blockIdx.x * 128;

    float2 acc[8][4];                // [token j][latent-pair p], l = lt*8 + 2p + lane
    #pragma unroll
    for (int j = 0; j < 8; ++j)
        #pragma unroll
        for (int p = 0; p < 4; ++p) acc[j][p] = make_float2(0.f, 0.f);

    for (int ch = 0; ch < 16; ++ch) {
        __syncthreads();
        #pragma unroll
        for (int s = 0; s < 8; ++s) {
            int id = tid + 128 * s;          // z chunk [128][32]
            int t = id >> 3, q = id & 7;
            float4 v = *(const float4*)(z + (size_t)(tok0 + t) * IN_D + ch * 32 + q * 4);
            *(float4*)(zs + t * 36 + q * 4) = v;
        }
        #pragma unroll
        for (int s = 0; s < 4; ++s) {
            int id = tid + 128 * s;          // ws chunk [32][64], natural
            int i = id >> 4, q = id & 15;
            float4 v = *(const float4*)(Wq + (size_t)(ch * 32 + i) * D_LAT + q * 4);
            *(float4*)(ws + i * ES_STR + q * 4) = v;
        }
        __syncthreads();

        #pragma unroll
        for (int iq = 0; iq < 8; ++iq) {
            float4 zv[8];
            #pragma unroll
            for (int j = 0; j < 8; ++j)
                zv[j] = *(const float4*)(zs + (tt + 16 * j) * 36 + iq * 4);
            #pragma unroll
            for (int ii = 0; ii < 4; ++ii) {
                int i = iq * 4 + ii;
                float4 wv0 = *(const float4*)(ws + i * ES_STR + lt * 8);
                float4 wv1 = *(const float4*)(ws + i * ES_STR + lt * 8 + 4);
                float2 wp0 = make_float2(wv0.x, wv0.y);
                float2 wp1 = make_float2(wv0.z, wv0.w);
                float2 wp2 = make_float2(wv1.x, wv1.y);
                float2 wp3 = make_float2(wv1.z, wv1.w);
                #pragma unroll
                for (int j = 0; j < 8; ++j) {
                    float zc = (ii == 0) ? zv[j].x : (ii == 1) ? zv[j].y : (ii == 2) ? zv[j].z : zv[j].w;
                    float2 z2 = make_float2(zc, zc);
                    acc[j][0] = ffma2(z2, wp0, acc[j][0]);
                    acc[j][1] = ffma2(z2, wp1, acc[j][1]);
                    acc[j][2] = ffma2(z2, wp2, acc[j][2]);
                    acc[j][3] = ffma2(z2, wp3, acc[j][3]);
                }
            }
        }
    }

    #pragma unroll
    for (int j = 0; j < 8; ++j) {
        int t = tok0 + tt + 16 * j;
        int l0 = lt * 8;
        float4 o0 = make_float4(acc[j][0].x + bq[l0 + 0], acc[j][0].y + bq[l0 + 1],
                                acc[j][1].x + bq[l0 + 2], acc[j][1].y + bq[l0 + 3]);
        float4 o1 = make_float4(acc[j][2].x + bq[l0 + 4], acc[j][2].y + bq[l0 + 5],
                                acc[j][3].x + bq[l0 + 6], acc[j][3].y + bq[l0 + 7]);
        *(float4*)(g_residual + (size_t)t * D_LAT + l0)     = o0;
        *(float4*)(g_residual + (size_t)t * D_LAT + l0 + 4) = o1;
    }
}

// ---------------- kernel C: residual VQ + final projection ----------------
// smem layout (floats):
//  rs    64*68     zqs  64*68     rstp 32*132
//  es    2*256*68  esq  2*256     rsq  64
//  bestv 64*32     besti 64*32    idx  64
#define SMEM_FLOATS (64*ES_STR + 64*ES_STR + 32*RP_STR + 2*256*ES_STR + 2*256 + 64 \
                     + 64*32 + 64*32 + 64)
#define SMEM_BYTES  (SMEM_FLOATS * 4)

__global__ void __launch_bounds__(256, 1) rcq_kernel(const float* __restrict__ cb,
                                                     const float* __restrict__ Wp,
                                                     const float* __restrict__ bp,
                                                     float* __restrict__ out) {
    extern __shared__ float sm[];
    float* rs    = sm;                        // [64][68]
    float* zqs   = rs + 64 * ES_STR;          // [64][68]
    float* rstp  = zqs + 64 * ES_STR;         // [32 pairs][132] token-pair-interleaved
    float* es    = rstp + 32 * RP_STR;        // 2 x [256][68]
    float* esqS  = es + 2 * 256 * ES_STR;     // 2 x [256]
    float* rsqS  = esqS + 512;                // [64]
    float* bestv = rsqS + 64;                 // [64][32]
    int*   besti = (int*)(bestv + 64 * 32);   // [64][32]
    int*   idxS  = besti + 64 * 32;           // [64]

    int tid = threadIdx.x;
    int pt = tid & 7;       // pair-thread: pairs pt+8m (m=0..3) -> tokens 2P, 2P+1
    int kg = tid >> 3;      // k-thread (32): k = kg + 32*i
    int tok0 = blockIdx.x * 64;

    // init rs from global residual, zqs = 0
    #pragma unroll
    for (int s = 0; s < 4; ++s) {
        int id = tid + 256 * s;
        int t = id >> 4, q = id & 15;
        float4 v = *(const float4*)(g_residual + (size_t)(tok0 + t) * D_LAT + q * 4);
        *(float4*)(rs + t * ES_STR + q * 4)  = v;
        *(float4*)(zqs + t * ES_STR + q * 4) = make_float4(0.f, 0.f, 0.f, 0.f);
    }
    __syncthreads();

    // prefetch chunk 0
    {
        const float* src = cb;
        float* dst = es;
        #pragma unroll
        for (int s = 0; s < 16; ++s) {
            int id = tid + 256 * s;
            int r = id >> 4, q = id & 15;
            cpa16(dst + r * ES_STR + q * 4, src + (size_t)r * D_LAT + q * 4);
        }
        if (tid < 64) cpa16(esqS + tid * 4, g_esq + tid * 4);
        cp_commit();
    }

    for (int h = 0; h < H_CB; ++h) {
        // rebuild token-pair layout + rsq (rs is stable here)
        #pragma unroll
        for (int s = 0; s < 8; ++s) {
            int id = tid + 256 * s;          // 0..2047: P = id>>6, d = id&63
            int P = id >> 6, d = id & 63;
            rstp[P * RP_STR + 2 * d]     = rs[(2 * P) * ES_STR + d];
            rstp[P * RP_STR + 2 * d + 1] = rs[(2 * P + 1) * ES_STR + d];
        }
        if (tid < 64) {
            const float* r = rs + tid * ES_STR;
            float a = 0.f;
            #pragma unroll
            for (int d = 0; d < 64; ++d) a = fmaf(r[d], r[d], a);
            rsqS[tid] = a;
        }
        // (visibility of rstp/rsq guaranteed by the per-chunk sync below)

        float bv[8]; int bi[8];              // 8 token slots: 2m + lane
        #pragma unroll
        for (int j = 0; j < 8; ++j) { bv[j] = FLT_MAX; bi[j] = 0x7fffffff; }

        for (int ch = 0; ch < 16; ++ch) {
            int g = h * 16 + ch;
            // prefetch next chunk (global sequence) into the other buffer
            if (g + 1 < 64) {
                int h2 = (g + 1) >> 4, c2 = (g + 1) & 15;
                const float* src = cb + ((size_t)h2 * K_CB + c2 * 256) * D_LAT;
                float* dst = es + ((g + 1) & 1) * (256 * ES_STR);
                #pragma unroll
                for (int s = 0; s < 16; ++s) {
                    int id = tid + 256 * s;
                    int r = id >> 4, q = id & 15;
                    cpa16(dst + r * ES_STR + q * 4, src + (size_t)r * D_LAT + q * 4);
                }
                if (tid < 64)
                    cpa16(esqS + ((g + 1) & 1) * 256 + tid * 4,
                          g_esq + h2 * K_CB + c2 * 256 + tid * 4);
            }
            cp_commit();
            cp_wait<1>();          // current chunk's group has landed
            __syncthreads();

            const float* esb  = es + (g & 1) * (256 * ES_STR);
            const float* esqb = esqS + (g & 1) * 256;
            int kbase = ch * 256;

            float2 acc[4][8];
            #pragma unroll
            for (int m = 0; m < 4; ++m)
                #pragma unroll
                for (int i = 0; i < 8; ++i) acc[m][i] = make_float2(0.f, 0.f);

            #pragma unroll 4
            for (int d4 = 0; d4 < 16; ++d4) {
                float4 ev[8];
                #pragma unroll
                for (int i = 0; i < 8; ++i)
                    ev[i] = *(const float4*)(esb + (kg + 32 * i) * ES_STR + d4 * 4);
                float4 rpA[4], rpB[4];
                #pragma unroll
                for (int m = 0; m < 4; ++m) {
                    rpA[m] = *(const float4*)(rstp + (pt + 8 * m) * RP_STR + d4 * 8);
                    rpB[m] = *(const float4*)(rstp + (pt + 8 * m) * RP_STR + d4 * 8 + 4);
                }
                #pragma unroll
                for (int dd = 0; dd < 4; ++dd) {
                    #pragma unroll
                    for (int i = 0; i < 8; ++i) {
                        float e = (dd == 0) ? ev[i].x : (dd == 1) ? ev[i].y
                                : (dd == 2) ? ev[i].z : ev[i].w;
                        float2 e2 = make_float2(e, e);
                        #pragma unroll
                        for (int m = 0; m < 4; ++m) {
                            float2 r2;
                            if      (dd == 0) r2 = make_float2(rpA[m].x, rpA[m].y);
                            else if (dd == 1) r2 = make_float2(rpA[m].z, rpA[m].w);
                            else if (dd == 2) r2 = make_float2(rpB[m].x, rpB[m].y);
                            else              r2 = make_float2(rpB[m].z, rpB[m].w);
                            acc[m][i] = ffma2(r2, e2, acc[m][i]);
                        }
                    }
                }
            }

            // argmin update: d = (rsq + e_sq) - 2*dot, tie -> lowest index
            #pragma unroll
            for (int m = 0; m < 4; ++m) {
                float rq0 = rsqS[2 * (pt + 8 * m)];
                float rq1 = rsqS[2 * (pt + 8 * m) + 1];
                #pragma unroll
                for (int i = 0; i < 8; ++i) {
                    float eq = esqb[kg + 32 * i];
                    int kk = kbase + kg + 32 * i;
                    float dv0 = (rq0 + eq) - 2.0f * acc[m][i].x;
                    if (dv0 < bv[2*m] || (dv0 == bv[2*m] && kk < bi[2*m])) { bv[2*m] = dv0; bi[2*m] = kk; }
                    float dv1 = (rq1 + eq) - 2.0f * acc[m][i].y;
                    if (dv1 < bv[2*m+1] || (dv1 == bv[2*m+1] && kk < bi[2*m+1])) { bv[2*m+1] = dv1; bi[2*m+1] = kk; }
                }
            }
            __syncthreads();
        }

        // cross-thread argmin reduce
        #pragma unroll
        for (int m = 0; m < 4; ++m) {
            int t0 = 2 * (pt + 8 * m);
            bestv[t0 * 32 + kg] = bv[2*m];       besti[t0 * 32 + kg] = bi[2*m];
            bestv[(t0+1) * 32 + kg] = bv[2*m+1]; besti[(t0+1) * 32 + kg] = bi[2*m+1];
        }
        __syncthreads();
        if (tid < 64) {
            float v = bestv[tid * 32]; int bidx = besti[tid * 32];
            for (int gq = 1; gq < 32; ++gq) {
                float vv = bestv[tid * 32 + gq]; int ii = besti[tid * 32 + gq];
                if (vv < v || (vv == v && ii < bidx)) { v = vv; bidx = ii; }
            }
            idxS[tid] = bidx;
        }
        __syncthreads();
        // gather + update: zq += e, r -= e
        {
            int t = tid >> 2, q0 = (tid & 3) * 4;
            const float* e = cb + ((size_t)h * K_CB + idxS[t]) * D_LAT;
            #pragma unroll
            for (int q = 0; q < 4; ++q) {
                float4 evv = *(const float4*)(e + (q0 + q) * 4);
                float* zp = zqs + t * ES_STR + (q0 + q) * 4;
                float* rp = rs + t * ES_STR + (q0 + q) * 4;
                float4 zv = *(float4*)zp;
                float4 rw = *(float4*)rp;
                zv.x += evv.x; zv.y += evv.y; zv.z += evv.z; zv.w += evv.w;
                rw.x -= evv.x; rw.y -= evv.y; rw.z -= evv.z; rw.w -= evv.w;
                *(float4*)zp = zv;
                *(float4*)rp = rw;
            }
        }
        __syncthreads();
    }

    // ---------------- phase 3: out = zqs @ Wp + bp (f32x2, token pairs) ----------------
    // pack zq into token-pair layout (reuse rstp)
    #pragma unroll
    for (int s = 0; s < 8; ++s) {
        int id = tid + 256 * s;
        int P = id >> 6, d = id & 63;
        rstp[P * RP_STR + 2 * d]     = zqs[(2 * P) * ES_STR + d];
        rstp[P * RP_STR + 2 * d + 1] = zqs[(2 * P + 1) * ES_STR + d];
    }

    float* wps = es;   // reuse buffer 0 as [c][d], stride ES_STR
    for (int co = 0; co < IN_D; co += 256) {
        __syncthreads();
        #pragma unroll 8
        for (int s = 0; s < 64; ++s) {
            int id = tid + 256 * s;          // d = id>>8, c = id&255
            int d = id >> 8, c = id & 255;
            wps[c * ES_STR + d] = Wp[(size_t)d * IN_D + co + c];
        }
        __syncthreads();

        float2 acc[4][8];
        #pragma unroll
        for (int m = 0; m < 4; ++m)
            #pragma unroll
            for (int i = 0; i < 8; ++i) acc[m][i] = make_float2(0.f, 0.f);

        #pragma unroll 4
        for (int d4 = 0; d4 < 16; ++d4) {
            float4 wv[8];
            #pragma unroll
            for (int i = 0; i < 8; ++i)
                wv[i] = *(const float4*)(wps + (kg + 32 * i) * ES_STR + d4 * 4);
            float4 zpA[4], zpB[4];
            #pragma unroll
            for (int m = 0; m < 4; ++m) {
                zpA[m] = *(const float4*)(rstp + (pt + 8 * m) * RP_STR + d4 * 8);
                zpB[m] = *(const float4*)(rstp + (pt + 8 * m) * RP_STR + d4 * 8 + 4);
            }
            #pragma unroll
            for (int dd = 0; dd < 4; ++dd) {
                #pragma unroll
                for (int i = 0; i < 8; ++i) {
                    float w = (dd == 0) ? wv[i].x : (dd == 1) ? wv[i].y
                            : (dd == 2) ? wv[i].z : wv[i].w;
                    float2 w2 = make_float2(w, w);
                    #pragma unroll
                    for (int m = 0; m < 4; ++m) {
                        float2 z2;
                        if      (dd == 0) z2 = make_float2(zpA[m].x, zpA[m].y);
                        else if (dd == 1) z2 = make_float2(zpA[m].z, zpA[m].w);
                        else if (dd == 2) z2 = make_float2(zpB[m].x, zpB[m].y);
                        else              z2 = make_float2(zpB[m].z, zpB[m].w);
                        acc[m][i] = ffma2(z2, w2, acc[m][i]);
                    }
                }
            }
        }
        #pragma unroll
        for (int m = 0; m < 4; ++m) {
            int t0 = tok0 + 2 * (pt + 8 * m);
            #pragma unroll
            for (int i = 0; i < 8; ++i) {
                int c = co + kg + 32 * i;
                float b = bp[c];
                out[(size_t)t0 * IN_D + c]       = acc[m][i].x + b;
                out[(size_t)(t0 + 1) * IN_D + c] = acc[m][i].y + b;
            }
        }
    }
}

// ---------------- launcher ----------------
extern "C" void kernel_launch(void* const* d_in, const int* in_sizes, int n_in,
                              void* d_out, int out_size) {
    const float* z  = (const float*)d_in[0];
    const float* Wq = (const float*)d_in[1];
    const float* bq = (const float*)d_in[2];
    const float* cb = (const float*)d_in[3];
    const float* Wp = (const float*)d_in[4];
    const float* bp = (const float*)d_in[5];
    float* out = (float*)d_out;

    cudaFuncSetAttribute(rcq_kernel, cudaFuncAttributeMaxDynamicSharedMemorySize, SMEM_BYTES);

    esq_kernel<<<(H_CB * K_CB * 32 + 255) / 256, 256>>>(cb);
    proj_in_kernel<<<N_TOK / 128, 128>>>(z, Wq, bq);
    rcq_kernel<<<N_TOK / 64, 256, SMEM_BYTES>>>(cb, Wp, bp, out);
}